// round 1
// baseline (speedup 1.0000x reference)
#include <cuda_runtime.h>
#include <cuda_bf16.h>
#include <math.h>

// Problem constants
#define BATCH 4
#define CCH   512
#define HW    4096
#define NGRP  32
#define CPG   16          // channels per group
#define EPSV  1e-6f

// ---------------------------------------------------------------------------
// Scratch (static __device__ globals: allocation-guard safe)
// ---------------------------------------------------------------------------
__device__ float g_hn  [(size_t)BATCH * CCH * HW];          // 33.5 MB
__device__ float g_q   [(size_t)BATCH * CCH * HW];
__device__ float g_k   [(size_t)BATCH * CCH * HW];
__device__ float g_v   [(size_t)BATCH * CCH * HW];
__device__ float g_attn[(size_t)BATCH * HW  * HW];          // 268 MB
__device__ float g_o   [(size_t)BATCH * CCH * HW];

// ---------------------------------------------------------------------------
// GroupNorm: one block per (batch, group). Two-pass (sum/sumsq, then write).
// ---------------------------------------------------------------------------
__global__ __launch_bounds__(512) void groupnorm_kernel(
    const float* __restrict__ x, const float* __restrict__ scale,
    const float* __restrict__ bias, float* __restrict__ out)
{
    const int g = blockIdx.x % NGRP;
    const int b = blockIdx.x / NGRP;
    const size_t base = ((size_t)b * CCH + (size_t)g * CPG) * HW;
    const float* xp = x + base;
    float* op = out + base;
    const int tid = threadIdx.x;
    const int NT = 512;
    const int NE = CPG * HW;  // 65536

    float s = 0.f, ss = 0.f;
    for (int i = tid; i < NE; i += NT) {
        float v = xp[i];
        s += v;
        ss += v * v;
    }
    __shared__ float red[512];
    red[tid] = s; __syncthreads();
    for (int o = NT / 2; o > 0; o >>= 1) {
        if (tid < o) red[tid] += red[tid + o];
        __syncthreads();
    }
    const float mean = red[0] * (1.f / NE);
    __syncthreads();
    red[tid] = ss; __syncthreads();
    for (int o = NT / 2; o > 0; o >>= 1) {
        if (tid < o) red[tid] += red[tid + o];
        __syncthreads();
    }
    const float var = red[0] * (1.f / NE) - mean * mean;
    const float inv = rsqrtf(var + EPSV);

    // per-channel fused affine: out = x * a + c
    __shared__ float sa[CPG], sc[CPG];
    if (tid < CPG) {
        float scl = scale[g * CPG + tid];
        float bia = bias[g * CPG + tid];
        sa[tid] = scl * inv;
        sc[tid] = bia - mean * inv * scl;
    }
    __syncthreads();

    for (int i = tid; i < NE; i += NT) {
        int c = i >> 12;  // i / HW
        op[i] = xp[i] * sa[c] + sc[c];
    }
}

// ---------------------------------------------------------------------------
// Row softmax over attn: one block (256 thr) per row of 4096; row held in regs.
// ---------------------------------------------------------------------------
__global__ __launch_bounds__(256) void softmax_kernel(float* __restrict__ S)
{
    float* p = S + (size_t)blockIdx.x * HW;
    const int tid = threadIdx.x;
    float vals[16];
    float m = -1e30f;
#pragma unroll
    for (int i = 0; i < 16; i++) {
        vals[i] = p[tid + i * 256];
        m = fmaxf(m, vals[i]);
    }
    __shared__ float red[256];
    red[tid] = m; __syncthreads();
    for (int o = 128; o > 0; o >>= 1) {
        if (tid < o) red[tid] = fmaxf(red[tid], red[tid + o]);
        __syncthreads();
    }
    m = red[0];
    __syncthreads();
    float s = 0.f;
#pragma unroll
    for (int i = 0; i < 16; i++) {
        vals[i] = __expf(vals[i] - m);
        s += vals[i];
    }
    red[tid] = s; __syncthreads();
    for (int o = 128; o > 0; o >>= 1) {
        if (tid < o) red[tid] += red[tid + o];
        __syncthreads();
    }
    const float invs = 1.f / red[0];
#pragma unroll
    for (int i = 0; i < 16; i++)
        p[tid + i * 256] = vals[i] * invs;
}

// ---------------------------------------------------------------------------
// Tiled SGEMM: C[m,n] = alpha * sum_k A(m,k) * B(k,n)  (+bias[m]) (+resid)
//   TA=0: A(m,k) = A[m*lda + k]   TA=1: A(m,k) = A[k*lda + m]
//   TB=0: B(k,n) = B[k*ldb + n]   TB=1: B(k,n) = B[n*ldb + k]
// 128x128 block tile, KT=16, 256 threads, 8x8 per-thread microtile.
// All dims are multiples of 128 (M in {512,1536,4096}) -> no bounds checks.
// ---------------------------------------------------------------------------
template<bool TA, bool TB>
__global__ __launch_bounds__(256, 2) void sgemm_kernel(
    const float* __restrict__ A, const float* __restrict__ Bm,
    const float* __restrict__ bias, const float* __restrict__ resid,
    float* __restrict__ Cm,
    int M, int N, int K, int lda, int ldb, int ldc,
    size_t bsA, size_t bsB, size_t bsC, float alpha)
{
    constexpr int KT = 16;
    __shared__ float As[KT][132];
    __shared__ float Bs[KT][132];

    const int bz = blockIdx.z;
    A  += bsA * bz;
    Bm += bsB * bz;
    Cm += bsC * bz;
    const float* R = resid ? (resid + bsC * bz) : nullptr;

    const int m0 = blockIdx.y * 128;
    const int n0 = blockIdx.x * 128;
    const int tid = threadIdx.x;
    const int tx = tid & 15;
    const int ty = tid >> 4;

    float acc[8][8];
#pragma unroll
    for (int r = 0; r < 8; r++)
#pragma unroll
        for (int c = 0; c < 8; c++) acc[r][c] = 0.f;

    for (int k0 = 0; k0 < K; k0 += KT) {
        // ---- stage A tile: As[kk][m] ----
        if (TA) {
#pragma unroll
            for (int l = 0; l < 8; l++) {
                int i = tid + l * 256;
                int kk = i >> 7, m = i & 127;
                As[kk][m] = A[(size_t)(k0 + kk) * lda + (m0 + m)];
            }
        } else {
#pragma unroll
            for (int l = 0; l < 8; l++) {
                int i = tid + l * 256;
                int m = i >> 4, kk = i & 15;
                As[kk][m] = A[(size_t)(m0 + m) * lda + (k0 + kk)];
            }
        }
        // ---- stage B tile: Bs[kk][n] ----
        if (TB) {
#pragma unroll
            for (int l = 0; l < 8; l++) {
                int i = tid + l * 256;
                int n = i >> 4, kk = i & 15;
                Bs[kk][n] = Bm[(size_t)(n0 + n) * ldb + (k0 + kk)];
            }
        } else {
#pragma unroll
            for (int l = 0; l < 8; l++) {
                int i = tid + l * 256;
                int kk = i >> 7, n = i & 127;
                Bs[kk][n] = Bm[(size_t)(k0 + kk) * ldb + (n0 + n)];
            }
        }
        __syncthreads();

#pragma unroll
        for (int kk = 0; kk < KT; kk++) {
            float a[8], b[8];
            *(float4*)&a[0] = *(const float4*)&As[kk][ty * 8];
            *(float4*)&a[4] = *(const float4*)&As[kk][ty * 8 + 4];
            *(float4*)&b[0] = *(const float4*)&Bs[kk][tx * 8];
            *(float4*)&b[4] = *(const float4*)&Bs[kk][tx * 8 + 4];
#pragma unroll
            for (int r = 0; r < 8; r++)
#pragma unroll
                for (int c = 0; c < 8; c++)
                    acc[r][c] += a[r] * b[c];
        }
        __syncthreads();
    }

    // ---- epilogue ----
#pragma unroll
    for (int r = 0; r < 8; r++) {
        const int m = m0 + ty * 8 + r;
        const float bb = bias ? bias[m] : 0.f;
        const size_t rowoff = (size_t)m * ldc + n0 + tx * 8;
#pragma unroll
        for (int c = 0; c < 8; c++) {
            float v = acc[r][c] * alpha + bb;
            if (R) v += R[rowoff + c];
            Cm[rowoff + c] = v;
        }
    }
}

// ---------------------------------------------------------------------------
// Launch
// ---------------------------------------------------------------------------
extern "C" void kernel_launch(void* const* d_in, const int* in_sizes, int n_in,
                              void* d_out, int out_size)
{
    const float* x        = (const float*)d_in[0];
    const float* gn_scale = (const float*)d_in[1];
    const float* gn_bias  = (const float*)d_in[2];
    const float* wq       = (const float*)d_in[3];
    const float* bq       = (const float*)d_in[4];
    const float* wk       = (const float*)d_in[5];
    const float* bk       = (const float*)d_in[6];
    const float* wv       = (const float*)d_in[7];
    const float* bv       = (const float*)d_in[8];
    const float* wproj    = (const float*)d_in[9];
    const float* bproj    = (const float*)d_in[10];
    float* out = (float*)d_out;

    float *hn, *q, *k, *v, *attn, *o;
    cudaGetSymbolAddress((void**)&hn,   g_hn);
    cudaGetSymbolAddress((void**)&q,    g_q);
    cudaGetSymbolAddress((void**)&k,    g_k);
    cudaGetSymbolAddress((void**)&v,    g_v);
    cudaGetSymbolAddress((void**)&attn, g_attn);
    cudaGetSymbolAddress((void**)&o,    g_o);

    const size_t bsX = (size_t)CCH * HW;       // per-batch stride for [C,HW] mats
    const size_t bsS = (size_t)HW * HW;        // per-batch stride for attn

    // 1) GroupNorm
    groupnorm_kernel<<<BATCH * NGRP, 512>>>(x, gn_scale, gn_bias, hn);

    dim3 blk(256);

    // 2) Q,K,V = W(512x512) @ hn(512x4096)  [NN], per batch
    dim3 gQKV(HW / 128, CCH / 128, BATCH);
    sgemm_kernel<false, false><<<gQKV, blk>>>(wq, hn, bq, nullptr, q,
        CCH, HW, CCH, CCH, HW, HW, 0, bsX, bsX, 1.f);
    sgemm_kernel<false, false><<<gQKV, blk>>>(wk, hn, bk, nullptr, k,
        CCH, HW, CCH, CCH, HW, HW, 0, bsX, bsX, 1.f);
    sgemm_kernel<false, false><<<gQKV, blk>>>(wv, hn, bv, nullptr, v,
        CCH, HW, CCH, CCH, HW, HW, 0, bsX, bsX, 1.f);

    // 3) S[i,j] = scale * sum_c q[c,i] k[c,j]  [TN], per batch
    const float scale = 1.0f / sqrtf((float)CCH);
    dim3 gS(HW / 128, HW / 128, BATCH);
    sgemm_kernel<true, false><<<gS, blk>>>(q, k, nullptr, nullptr, attn,
        HW, HW, CCH, HW, HW, HW, bsX, bsX, bsS, scale);

    // 4) row softmax over S
    softmax_kernel<<<BATCH * HW, 256>>>(attn);

    // 5) O[c,i] = sum_j v[c,j] * attn[i,j]  [NT], per batch
    dim3 gO(HW / 128, CCH / 128, BATCH);
    sgemm_kernel<false, true><<<gO, blk>>>(v, attn, nullptr, nullptr, o,
        CCH, HW, HW, HW, HW, HW, bsX, bsS, bsX, 1.f);

    // 6) out = x + Wproj @ O + bproj  [NN + residual], per batch
    sgemm_kernel<false, false><<<gO, blk>>>(wproj, o, bproj, x, out,
        CCH, HW, CCH, CCH, HW, HW, 0, bsX, bsX, 1.f);
}

// round 3
// speedup vs baseline: 3.0490x; 3.0490x over previous
#include <cuda_runtime.h>
#include <cstdint>
#include <math.h>

// ---------------------------------------------------------------------------
// Problem constants
// ---------------------------------------------------------------------------
#define BATCH 4
#define CCH   512
#define HW    4096
#define NGRP  32
#define CPG   16
#define EPSV  1e-6f

// ---------------------------------------------------------------------------
// Scratch (static __device__ globals: allocation-guard safe)
//   g_hn  : hn^T  [b][hw][c]
//   g_q   : q^T   [b][hw][c]
//   g_k   : k^T   [b][hw][c]
//   g_v   : v     [b][c][hw]
//   g_o   : o^T   [b][hw][c]
//   g_attn: S     [b][i][j]
//   g_wr  : tf32-rounded weights  [4][c_out][c_in]  (q,k,v,proj)
// ---------------------------------------------------------------------------
__device__ float g_hn  [(size_t)BATCH * CCH * HW];
__device__ float g_q   [(size_t)BATCH * CCH * HW];
__device__ float g_k   [(size_t)BATCH * CCH * HW];
__device__ float g_v   [(size_t)BATCH * CCH * HW];
__device__ float g_o   [(size_t)BATCH * CCH * HW];
__device__ float g_attn[(size_t)BATCH * HW  * HW];
__device__ float g_wr  [(size_t)4 * CCH * CCH];

// ---------------------------------------------------------------------------
// Helpers
// ---------------------------------------------------------------------------
__device__ __forceinline__ uint32_t smem_u32(const void* p) {
    uint32_t a;
    asm("{ .reg .u64 t; cvta.to.shared.u64 t, %1; cvt.u32.u64 %0, t; }"
        : "=r"(a) : "l"(p));
    return a;
}

__device__ __forceinline__ float round_tf32(float x) {
    uint32_t u;
    asm("cvt.rna.tf32.f32 %0, %1;" : "=r"(u) : "f"(x));
    return __uint_as_float(u);
}

__device__ __forceinline__ void cp_async16(uint32_t dst, const void* src) {
    asm volatile("cp.async.cg.shared.global [%0], [%1], 16;"
                 :: "r"(dst), "l"(src) : "memory");
}
#define CP_COMMIT() asm volatile("cp.async.commit_group;" ::: "memory")
#define CP_WAIT(n)  asm volatile("cp.async.wait_group %0;" :: "n"(n) : "memory")

// tf32 mma m16n8k8: D(16x8,f32) += A(16x8,tf32) * B(8x8,tf32)
__device__ __forceinline__ void mma_tf32(float* d, const uint32_t* a,
                                         const uint32_t* b) {
    asm volatile(
        "mma.sync.aligned.m16n8k8.row.col.f32.tf32.tf32.f32 "
        "{%0,%1,%2,%3}, {%4,%5,%6,%7}, {%8,%9}, {%0,%1,%2,%3};"
        : "+f"(d[0]), "+f"(d[1]), "+f"(d[2]), "+f"(d[3])
        : "r"(a[0]), "r"(a[1]), "r"(a[2]), "r"(a[3]),
          "r"(b[0]), "r"(b[1]));
}

// ---------------------------------------------------------------------------
// GroupNorm (transposed output): hnT[b][hw][c], tf32-rounded.
// ---------------------------------------------------------------------------
__global__ __launch_bounds__(512) void groupnorm_t_kernel(
    const float* __restrict__ x, const float* __restrict__ scale,
    const float* __restrict__ bias, float* __restrict__ outT)
{
    const int g = blockIdx.x % NGRP;
    const int b = blockIdx.x / NGRP;
    const size_t base = ((size_t)b * CCH + (size_t)g * CPG) * HW;
    const float* xp = x + base;
    float* op = outT + (size_t)b * CCH * HW;
    const int tid = threadIdx.x;
    const int NE = CPG * HW;

    float s = 0.f, ss = 0.f;
    for (int i = tid; i < NE; i += 512) {
        float v = xp[i];
        s += v; ss += v * v;
    }
    __shared__ float red[512];
    red[tid] = s; __syncthreads();
    for (int o = 256; o > 0; o >>= 1) { if (tid < o) red[tid] += red[tid + o]; __syncthreads(); }
    const float mean = red[0] * (1.f / NE);
    __syncthreads();
    red[tid] = ss; __syncthreads();
    for (int o = 256; o > 0; o >>= 1) { if (tid < o) red[tid] += red[tid + o]; __syncthreads(); }
    const float var = red[0] * (1.f / NE) - mean * mean;
    const float inv = rsqrtf(var + EPSV);

    __shared__ float sa[CPG], sc[CPG];
    if (tid < CPG) {
        float scl = scale[g * CPG + tid];
        float bia = bias[g * CPG + tid];
        sa[tid] = scl * inv;
        sc[tid] = bia - mean * inv * scl;
    }
    __syncthreads();

    __shared__ float tile[CPG][257];
    for (int hw0 = 0; hw0 < HW; hw0 += 256) {
        for (int i = tid; i < CPG * 256; i += 512) {
            int c = i >> 8, hh = i & 255;
            tile[c][hh] = xp[(size_t)c * HW + hw0 + hh];
        }
        __syncthreads();
        for (int i = tid; i < 256 * CPG; i += 512) {
            int hh = i >> 4, c = i & 15;
            float v = tile[c][hh] * sa[c] + sc[c];
            op[(size_t)(hw0 + hh) * CCH + g * CPG + c] = round_tf32(v);
        }
        __syncthreads();
    }
}

// ---------------------------------------------------------------------------
// Row softmax (tf32-rounded output since attn feeds the next GEMM)
// ---------------------------------------------------------------------------
__global__ __launch_bounds__(256) void softmax_kernel(float* __restrict__ S)
{
    float* p = S + (size_t)blockIdx.x * HW;
    const int tid = threadIdx.x;
    float vals[16];
    float m = -1e30f;
#pragma unroll
    for (int i = 0; i < 16; i++) {
        vals[i] = p[tid + i * 256];
        m = fmaxf(m, vals[i]);
    }
    __shared__ float red[256];
    red[tid] = m; __syncthreads();
    for (int o = 128; o > 0; o >>= 1) { if (tid < o) red[tid] = fmaxf(red[tid], red[tid + o]); __syncthreads(); }
    m = red[0];
    __syncthreads();
    float s = 0.f;
#pragma unroll
    for (int i = 0; i < 16; i++) { vals[i] = __expf(vals[i] - m); s += vals[i]; }
    red[tid] = s; __syncthreads();
    for (int o = 128; o > 0; o >>= 1) { if (tid < o) red[tid] += red[tid + o]; __syncthreads(); }
    const float invs = 1.f / red[0];
#pragma unroll
    for (int i = 0; i < 16; i++)
        p[tid + i * 256] = round_tf32(vals[i] * invs);
}

// ---------------------------------------------------------------------------
// Weight pre-rounding (q,k,v,proj -> g_wr, tf32 rna)
// ---------------------------------------------------------------------------
__global__ __launch_bounds__(256) void round_weights_kernel(
    const float* __restrict__ w0, const float* __restrict__ w1,
    const float* __restrict__ w2, const float* __restrict__ w3,
    float* __restrict__ out)
{
    const int i = blockIdx.x * 256 + threadIdx.x;
    const int which = i >> 18;
    const int idx = i & 262143;
    const float* src = (which == 0) ? w0 : (which == 1) ? w1 : (which == 2) ? w2 : w3;
    out[i] = round_tf32(src[idx]);
}

// ---------------------------------------------------------------------------
// tf32 mma.sync GEMM: C[m,n] = alpha * sum_k A[m,k]*B[n,k]
//                             + bias_m[m] + bias_n[n] + resid[m,n]
// A: [M,K] K-major, B: [N,K] K-major, C row-major.
// 128x128 block tile, KT=32, cp.async double-buffered, 256 threads (8 warps).
// Warp grid 2x4; each warp: 64x32 tile = 4x4 of m16n8k8 per k-step.
// Inputs must be tf32(rna)-pre-rounded.
// ---------------------------------------------------------------------------
#define KT 32
#define SROW 36                          // floats per smem row (pad 32 -> 36)
#define TILE_F (128 * SROW)              // floats per operand buffer
#define TILE_BY (TILE_F * 4)             // 18432 bytes

__global__ __launch_bounds__(256, 2) void tc_gemm_kernel(
    const float* __restrict__ A, const float* __restrict__ B,
    const float* __restrict__ bias_m, const float* __restrict__ bias_n,
    const float* __restrict__ resid, float* __restrict__ C,
    int K, int lda, int ldb, int ldc,
    size_t bsA, size_t bsB, size_t bsC,
    float alpha, int round_out)
{
    extern __shared__ float smem[];
    float* sA[2] = { smem,             smem + TILE_F };
    float* sB[2] = { smem + 2*TILE_F,  smem + 3*TILE_F };
    const uint32_t sA_u[2] = { smem_u32(sA[0]), smem_u32(sA[1]) };
    const uint32_t sB_u[2] = { smem_u32(sB[0]), smem_u32(sB[1]) };

    const int tid = threadIdx.x;
    const int wid = tid >> 5;
    const int lane = tid & 31;
    const int bz = blockIdx.z;

    A += bsA * bz;
    B += bsB * bz;
    C += bsC * bz;
    const float* R = resid ? (resid + bsC * bz) : nullptr;

    const int m0 = blockIdx.y * 128;
    const int n0 = blockIdx.x * 128;

    // warp tile origin within the 128x128 block
    const int wm = (wid >> 2) * 64;      // 0 or 64
    const int wn = (wid & 3) * 32;       // 0,32,64,96

    const int lrow = lane >> 2;          // 0..7
    const int lcol = lane & 3;           // 0..3

    float acc[4][4][4];                  // [mt][nt][frag]
#pragma unroll
    for (int mt = 0; mt < 4; mt++)
#pragma unroll
        for (int nt = 0; nt < 4; nt++)
#pragma unroll
            for (int f = 0; f < 4; f++) acc[mt][nt][f] = 0.f;

    const int nst = K / KT;

    // staging task decomposition: 1024 float4 per operand, 4 per thread
    const int srow0 = tid >> 3;          // base row for this thread's tasks
    const int scid = tid & 7;            // float4 column 0..7

    // ---- prologue: stage 0 ----
    {
        const float* Ag = A + (size_t)m0 * lda;
        const float* Bg = B + (size_t)n0 * ldb;
#pragma unroll
        for (int t = 0; t < 4; t++) {
            int row = srow0 + t * 32;
            cp_async16(sA_u[0] + (row * SROW + scid * 4) * 4,
                       Ag + (size_t)row * lda + scid * 4);
            cp_async16(sB_u[0] + (row * SROW + scid * 4) * 4,
                       Bg + (size_t)row * ldb + scid * 4);
        }
        CP_COMMIT();
    }

    for (int s = 0; s < nst; s++) {
        // prefetch next stage
        if (s + 1 < nst) {
            const int k0 = (s + 1) * KT;
            const int nb = (s + 1) & 1;
            const float* Ag = A + (size_t)m0 * lda + k0;
            const float* Bg = B + (size_t)n0 * ldb + k0;
#pragma unroll
            for (int t = 0; t < 4; t++) {
                int row = srow0 + t * 32;
                cp_async16(sA_u[nb] + (row * SROW + scid * 4) * 4,
                           Ag + (size_t)row * lda + scid * 4);
                cp_async16(sB_u[nb] + (row * SROW + scid * 4) * 4,
                           Bg + (size_t)row * ldb + scid * 4);
            }
            CP_COMMIT();
            CP_WAIT(1);
        } else {
            CP_WAIT(0);
        }
        __syncthreads();

        const float* As = sA[s & 1];
        const float* Bs = sB[s & 1];

#pragma unroll
        for (int ks = 0; ks < 4; ks++) {
            const int kb = ks * 8;
            uint32_t af[4][4];           // [mt][frag]
            uint32_t bf[4][2];           // [nt][frag]
#pragma unroll
            for (int mt = 0; mt < 4; mt++) {
                const int r0 = wm + mt * 16 + lrow;
                af[mt][0] = __float_as_uint(As[r0 * SROW + kb + lcol]);
                af[mt][1] = __float_as_uint(As[(r0 + 8) * SROW + kb + lcol]);
                af[mt][2] = __float_as_uint(As[r0 * SROW + kb + lcol + 4]);
                af[mt][3] = __float_as_uint(As[(r0 + 8) * SROW + kb + lcol + 4]);
            }
#pragma unroll
            for (int nt = 0; nt < 4; nt++) {
                const int c0 = wn + nt * 8 + lrow;
                bf[nt][0] = __float_as_uint(Bs[c0 * SROW + kb + lcol]);
                bf[nt][1] = __float_as_uint(Bs[c0 * SROW + kb + lcol + 4]);
            }
#pragma unroll
            for (int mt = 0; mt < 4; mt++)
#pragma unroll
                for (int nt = 0; nt < 4; nt++)
                    mma_tf32(acc[mt][nt], af[mt], bf[nt]);
        }
        __syncthreads();
    }

    // ---- epilogue ----
    // thread owns rows m0+wm+mt*16+lrow(+8), cols n0+wn+nt*8+2*lcol(+1)
#pragma unroll
    for (int mt = 0; mt < 4; mt++) {
#pragma unroll
        for (int half = 0; half < 2; half++) {
            const int m = m0 + wm + mt * 16 + lrow + half * 8;
            const float bm = bias_m ? bias_m[m] : 0.f;
            float* Crow = C + (size_t)m * ldc;
            const float* Rrow = R ? (R + (size_t)m * ldc) : nullptr;
#pragma unroll
            for (int nt = 0; nt < 4; nt++) {
                const int n = n0 + wn + nt * 8 + 2 * lcol;
                float v0 = acc[mt][nt][half * 2 + 0] * alpha + bm;
                float v1 = acc[mt][nt][half * 2 + 1] * alpha + bm;
                if (bias_n) { v0 += bias_n[n]; v1 += bias_n[n + 1]; }
                if (Rrow)   { v0 += Rrow[n];   v1 += Rrow[n + 1]; }
                if (round_out) { v0 = round_tf32(v0); v1 = round_tf32(v1); }
                *(float2*)(Crow + n) = make_float2(v0, v1);
            }
        }
    }
}

// ---------------------------------------------------------------------------
// Launch
// ---------------------------------------------------------------------------
extern "C" void kernel_launch(void* const* d_in, const int* in_sizes, int n_in,
                              void* d_out, int out_size)
{
    const float* x        = (const float*)d_in[0];
    const float* gn_scale = (const float*)d_in[1];
    const float* gn_bias  = (const float*)d_in[2];
    const float* wq       = (const float*)d_in[3];
    const float* bq       = (const float*)d_in[4];
    const float* wk       = (const float*)d_in[5];
    const float* bk       = (const float*)d_in[6];
    const float* wv       = (const float*)d_in[7];
    const float* bv       = (const float*)d_in[8];
    const float* wproj    = (const float*)d_in[9];
    const float* bproj    = (const float*)d_in[10];
    float* out = (float*)d_out;

    float *hn, *q, *k, *v, *o, *attn, *wr;
    cudaGetSymbolAddress((void**)&hn,   g_hn);
    cudaGetSymbolAddress((void**)&q,    g_q);
    cudaGetSymbolAddress((void**)&k,    g_k);
    cudaGetSymbolAddress((void**)&v,    g_v);
    cudaGetSymbolAddress((void**)&o,    g_o);
    cudaGetSymbolAddress((void**)&attn, g_attn);
    cudaGetSymbolAddress((void**)&wr,   g_wr);

    const float* wq_r = wr;
    const float* wk_r = wr + (size_t)CCH * CCH;
    const float* wv_r = wr + (size_t)2 * CCH * CCH;
    const float* wp_r = wr + (size_t)3 * CCH * CCH;

    const size_t bsX = (size_t)CCH * HW;
    const size_t bsS = (size_t)HW * HW;
    const int smem_bytes = 4 * TILE_BY;   // 73728

    cudaFuncSetAttribute(tc_gemm_kernel,
                         cudaFuncAttributeMaxDynamicSharedMemorySize, smem_bytes);

    // 0) round weights to tf32
    round_weights_kernel<<<(4 * CCH * CCH) / 256, 256>>>(wq, wk, wv, wproj, wr);

    // 1) GroupNorm -> hnT [hw][c], rounded
    groupnorm_t_kernel<<<BATCH * NGRP, 512>>>(x, gn_scale, gn_bias, hn);

    const float attn_scale = 1.0f / sqrtf((float)CCH);

    // 2) qT = hnT @ Wq^T : M=HW, N=C, K=C  (bias per n = bq)
    dim3 gQK(CCH / 128, HW / 128, BATCH);
    tc_gemm_kernel<<<gQK, 256, smem_bytes>>>(hn, wq_r, nullptr, bq, nullptr, q,
        CCH, CCH, CCH, CCH, bsX, 0, bsX, 1.f, 1);
    // 3) kT
    tc_gemm_kernel<<<gQK, 256, smem_bytes>>>(hn, wk_r, nullptr, bk, nullptr, k,
        CCH, CCH, CCH, CCH, bsX, 0, bsX, 1.f, 1);
    // 4) v = Wv @ hn : M=C, N=HW, K=C  (bias per m = bv)
    dim3 gV(HW / 128, CCH / 128, BATCH);
    tc_gemm_kernel<<<gV, 256, smem_bytes>>>(wv_r, hn, bv, nullptr, nullptr, v,
        CCH, CCH, CCH, HW, 0, bsX, bsX, 1.f, 1);

    // 5) S = qT @ kT^T * scale : M=HW, N=HW, K=C
    dim3 gS(HW / 128, HW / 128, BATCH);
    tc_gemm_kernel<<<gS, 256, smem_bytes>>>(q, k, nullptr, nullptr, nullptr, attn,
        CCH, CCH, CCH, HW, bsX, bsX, bsS, attn_scale, 0);

    // 6) softmax rows of S (rounded output)
    softmax_kernel<<<BATCH * HW, 256>>>(attn);

    // 7) oT = attn @ v^T : M=HW, N=C, K=HW
    dim3 gO(CCH / 128, HW / 128, BATCH);
    tc_gemm_kernel<<<gO, 256, smem_bytes>>>(attn, v, nullptr, nullptr, nullptr, o,
        HW, HW, HW, CCH, bsS, bsX, bsX, 1.f, 1);

    // 8) out = Wp @ oT^T + bproj + x : M=C, N=HW, K=C
    dim3 gP(HW / 128, CCH / 128, BATCH);
    tc_gemm_kernel<<<gP, 256, smem_bytes>>>(wp_r, o, bproj, nullptr, x, out,
        CCH, CCH, CCH, HW, 0, bsX, bsX, 1.f, 0);
}